// round 5
// baseline (speedup 1.0000x reference)
#include <cuda_runtime.h>
#include <math.h>

// Problem constants
#define BS 16
#define L  8192
#define D  512
#define NROWS (BS * L)          // 131072 timestep-rows
#define CHUNK 128               // timesteps per chunk
#define NCHUNKS (NROWS / CHUNK) // 1024
#define CPR (L / CHUNK)         // 64 chunks per batch row
#define TAU 2.0f
#define NEG -10000.0f
#define FN_ID 0xE4u             // identity fn: 0,1,2,3 -> 0,1,2,3

// Scratch (device globals — no allocation). SoA logits for coalesced access.
__device__ float g_l0[NROWS];
__device__ float g_l1[NROWS];
__device__ unsigned char g_chunkfn[NCHUNKS];

// fn: {0..3}->{0..3} packed 2 bits/entry. compose(first, second)(s) = second(first(s))
__device__ __forceinline__ unsigned compose_fn(unsigned first, unsigned second) {
    unsigned r = 0;
#pragma unroll
    for (int s = 0; s < 4; s++) {
        unsigned fs = (first >> (2 * s)) & 3u;
        r |= ((second >> (2 * fs)) & 3u) << (2 * s);
    }
    return r;
}

__device__ __forceinline__ unsigned step_fn(float l0, float l1) {
    unsigned u = (l1 > l0) ? 1u : 0u;           // decision if flag==0
    unsigned m = ((l1 + NEG) > l0) ? 1u : 0u;   // decision if flag>0
    unsigned e0 = u ? 3u : 0u;
    unsigned e1 = m ? 3u : 0u;
    unsigned e2 = m ? 3u : 1u;
    unsigned e3 = m ? 3u : 2u;
    return e0 | (e1 << 2) | (e2 << 4) | (e3 << 6);
}

// ---------------------------------------------------------------------------
// Kernel 1: pure GEMV. One warp per row (single row at a time — max occupancy
// for an HBM-bound stream; 4 LDG.128 in flight per lane is enough per warp).
// ---------------------------------------------------------------------------
__global__ void __launch_bounds__(256) gemv_kernel(
    const float* __restrict__ x,
    const float* __restrict__ W,
    const float* __restrict__ bias)
{
    __shared__ float sW[D * 2];
    int tid = threadIdx.x;
    for (int i = tid; i < D * 2; i += 256) sW[i] = W[i];
    __syncthreads();

    const int lane = tid & 31;
    const int warp = tid >> 5;

    // per-lane W slice: d = lane*4 + k*128 + j
    float w0[16], w1[16];
#pragma unroll
    for (int k = 0; k < 4; k++)
#pragma unroll
        for (int j = 0; j < 4; j++) {
            int d = lane * 4 + k * 128 + j;
            w0[k * 4 + j] = sW[d * 2 + 0];
            w1[k * 4 + j] = sW[d * 2 + 1];
        }
    const float b0 = bias[0], b1 = bias[1];

    const int gwarp  = blockIdx.x * 8 + warp;
    const int nwarps = gridDim.x * 8;

#pragma unroll 1
    for (int row = gwarp; row < NROWS; row += nwarps) {
        const float4* xp = reinterpret_cast<const float4*>(x + (size_t)row * D);
        float a0 = 0.f, a1 = 0.f;
#pragma unroll
        for (int k = 0; k < 4; k++) {
            float4 v = xp[lane + k * 32];
            a0 = fmaf(v.x, w0[k*4+0], a0); a1 = fmaf(v.x, w1[k*4+0], a1);
            a0 = fmaf(v.y, w0[k*4+1], a0); a1 = fmaf(v.y, w1[k*4+1], a1);
            a0 = fmaf(v.z, w0[k*4+2], a0); a1 = fmaf(v.z, w1[k*4+2], a1);
            a0 = fmaf(v.w, w0[k*4+3], a0); a1 = fmaf(v.w, w1[k*4+3], a1);
        }
#pragma unroll
        for (int off = 16; off > 0; off >>= 1) {
            a0 += __shfl_down_sync(0xffffffffu, a0, off);
            a1 += __shfl_down_sync(0xffffffffu, a1, off);
        }
        if (lane == 0) {
            g_l0[row] = a0 + b0;
            g_l1[row] = a1 + b1;
        }
    }
}

// ---------------------------------------------------------------------------
// Kernel 2: per-chunk transition function. One warp per 128-step chunk.
// Ordered reduce with ASCENDING offsets (contiguous segments only).
// ---------------------------------------------------------------------------
__global__ void __launch_bounds__(256) chunkfn_kernel()
{
    const int lane  = threadIdx.x & 31;
    const int warp  = threadIdx.x >> 5;
    const int chunk = blockIdx.x * 8 + warp;     // grid = 128 blocks

    const size_t base = (size_t)chunk * CHUNK + (size_t)lane * 4;
    float4 v0 = *reinterpret_cast<const float4*>(g_l0 + base);
    float4 v1 = *reinterpret_cast<const float4*>(g_l1 + base);

    unsigned f = step_fn(v0.x, v1.x);
    f = compose_fn(f, step_fn(v0.y, v1.y));
    f = compose_fn(f, step_fn(v0.z, v1.z));
    f = compose_fn(f, step_fn(v0.w, v1.w));

    // ordered tree reduce: lane 0 ends with f0∘f1∘...∘f31 (time order)
#pragma unroll
    for (int off = 1; off < 32; off <<= 1) {
        unsigned other = __shfl_down_sync(0xffffffffu, f, off);
        f = compose_fn(f, other);
    }
    if (lane == 0) g_chunkfn[chunk] = (unsigned char)f;
}

// ---------------------------------------------------------------------------
// Kernel 3: replay. 1024 blocks x 128 threads. Warp shfl scans.
// ---------------------------------------------------------------------------
__global__ void __launch_bounds__(128) replay_kernel(float* __restrict__ out)
{
    const int blk  = blockIdx.x;
    const int row  = blk / CPR;
    const int c    = blk % CPR;
    const int t    = threadIdx.x;
    const int lane = t & 31;
    const int w    = t >> 5;

    __shared__ unsigned sAgg[4];
    __shared__ unsigned s_inflag;

    const size_t base = (size_t)row * L + (size_t)c * CHUNK;

    const float l0 = g_l0[base + t];
    const float l1 = g_l1[base + t];

    // warp inclusive scan of step functions (time order = lane order)
    unsigned incl = step_fn(l0, l1);
#pragma unroll
    for (int off = 1; off < 32; off <<= 1) {
        unsigned p = __shfl_up_sync(0xffffffffu, incl, off);
        if (lane >= off) incl = compose_fn(p, incl);
    }
    if (lane == 31) sAgg[w] = incl;

    // warp 0: incoming flag = composition of cf[row*CPR .. row*CPR+c-1] applied to 0.
    if (w == 0) {
        const unsigned char* cf = g_chunkfn + row * CPR;
        unsigned a = (2 * lane     < c) ? (unsigned)cf[2 * lane]     : FN_ID;
        unsigned b = (2 * lane + 1 < c) ? (unsigned)cf[2 * lane + 1] : FN_ID;
        unsigned v = compose_fn(a, b);
#pragma unroll
        for (int off = 1; off < 32; off <<= 1) {
            unsigned p = __shfl_up_sync(0xffffffffu, v, off);
            if (lane >= off) v = compose_fn(p, v);
        }
        int src = ((c + 1) >> 1) - 1;                 // ceil(c/2)-1 (valid for c>0)
        unsigned F = __shfl_sync(0xffffffffu, v, src < 0 ? 0 : src);
        if (lane == 0) s_inflag = (c == 0) ? 0u : (F & 3u);
    }
    __syncthreads();

    // prefix of preceding warps (<=3 composes, contiguous order)
    unsigned wpre = FN_ID;
#pragma unroll
    for (int ww = 0; ww < 3; ww++)
        if (ww < w) wpre = compose_fn(wpre, sAgg[ww]);

    // exclusive within warp
    unsigned ex = __shfl_up_sync(0xffffffffu, incl, 1);
    if (lane == 0) ex = FN_ID;
    unsigned X = compose_fn(wpre, ex);

    const unsigned inflag = s_inflag;
    unsigned flag = (X >> (2 * inflag)) & 3u;

    float lm1 = (flag > 0u) ? (l1 + NEG) : l1;
    int pred = (lm1 > l0) ? 1 : 0;

    float mx    = fmaxf(l0, lm1);
    float other = pred ? l0 : lm1;
    float g = -log1pf(expf((other - mx) * (1.0f / TAU)));

    out[base + t]                 = (float)pred;
    out[(size_t)NROWS + base + t] = g;
}

// ---------------------------------------------------------------------------
extern "C" void kernel_launch(void* const* d_in, const int* in_sizes, int n_in,
                              void* d_out, int out_size)
{
    const float* x    = (const float*)d_in[0];   // [16, 8192, 512] f32
    // d_in[1] = label (int32) — unused
    const float* W    = (const float*)d_in[2];   // [512, 2] f32
    const float* bias = (const float*)d_in[3];   // [2] f32
    float* out = (float*)d_out;

    gemv_kernel<<<1024, 256>>>(x, W, bias);
    chunkfn_kernel<<<NCHUNKS / 8, 256>>>();
    replay_kernel<<<NCHUNKS, 128>>>(out);
}

// round 6
// speedup vs baseline: 1.0980x; 1.0980x over previous
#include <cuda_runtime.h>
#include <math.h>

// Problem constants
#define BS 16
#define L  8192
#define D  512
#define NROWS (BS * L)          // 131072 timestep-rows
#define CHUNK 128               // timesteps per chunk
#define NCHUNKS (NROWS / CHUNK) // 1024
#define CPR (L / CHUNK)         // 64 chunks per batch row
#define TAU 2.0f
#define NEG -10000.0f
#define FN_ID 0xE4u             // identity fn: 0,1,2,3 -> 0,1,2,3

#define GEMV_BLOCKS 1184        // 8 * 148 SMs

// Scratch (device globals — no allocation). SoA logits for coalesced access.
__device__ float g_l0[NROWS];
__device__ float g_l1[NROWS];
__device__ unsigned char g_chunkfn[NCHUNKS];

// fn: {0..3}->{0..3} packed 2 bits/entry. compose(first, second)(s) = second(first(s))
__device__ __forceinline__ unsigned compose_fn(unsigned first, unsigned second) {
    unsigned r = 0;
#pragma unroll
    for (int s = 0; s < 4; s++) {
        unsigned fs = (first >> (2 * s)) & 3u;
        r |= ((second >> (2 * fs)) & 3u) << (2 * s);
    }
    return r;
}

__device__ __forceinline__ unsigned step_fn(float l0, float l1) {
    unsigned u = (l1 > l0) ? 1u : 0u;           // decision if flag==0
    unsigned m = ((l1 + NEG) > l0) ? 1u : 0u;   // decision if flag>0
    unsigned e0 = u ? 3u : 0u;
    unsigned e1 = m ? 3u : 0u;
    unsigned e2 = m ? 3u : 1u;
    unsigned e3 = m ? 3u : 2u;
    return e0 | (e1 << 2) | (e2 << 4) | (e3 << 6);
}

// ---------------------------------------------------------------------------
// Kernel 1: GEMV, warp per row, software-pipelined: prefetch next row's
// 4 float4s before computing/reducing the current row so LDGs stay in flight
// through the compute tail.
// ---------------------------------------------------------------------------
__global__ void __launch_bounds__(256) gemv_kernel(
    const float* __restrict__ x,
    const float* __restrict__ W,
    const float* __restrict__ bias)
{
    __shared__ float sW[D * 2];
    int tid = threadIdx.x;
    for (int i = tid; i < D * 2; i += 256) sW[i] = W[i];
    __syncthreads();

    const int lane = tid & 31;
    const int warp = tid >> 5;

    // per-lane W slice: d = lane*4 + k*128 + j
    float w0[16], w1[16];
#pragma unroll
    for (int k = 0; k < 4; k++)
#pragma unroll
        for (int j = 0; j < 4; j++) {
            int d = lane * 4 + k * 128 + j;
            w0[k * 4 + j] = sW[d * 2 + 0];
            w1[k * 4 + j] = sW[d * 2 + 1];
        }
    const float b0 = bias[0], b1 = bias[1];

    const int gwarp  = blockIdx.x * 8 + warp;
    const int nwarps = GEMV_BLOCKS * 8;

    int row = gwarp;
    if (row >= NROWS) return;

    // prime the pipeline
    float4 v[4];
    {
        const float4* xp = reinterpret_cast<const float4*>(x + (size_t)row * D);
#pragma unroll
        for (int k = 0; k < 4; k++) v[k] = xp[lane + k * 32];
    }

#pragma unroll 1
    while (true) {
        const int nrow = row + nwarps;

        // prefetch next row (kept in flight during the compute tail below)
        float4 nv[4];
        if (nrow < NROWS) {
            const float4* np = reinterpret_cast<const float4*>(x + (size_t)nrow * D);
#pragma unroll
            for (int k = 0; k < 4; k++) nv[k] = np[lane + k * 32];
        }

        // compute current row
        float a0 = 0.f, a1 = 0.f;
#pragma unroll
        for (int k = 0; k < 4; k++) {
            a0 = fmaf(v[k].x, w0[k*4+0], a0); a1 = fmaf(v[k].x, w1[k*4+0], a1);
            a0 = fmaf(v[k].y, w0[k*4+1], a0); a1 = fmaf(v[k].y, w1[k*4+1], a1);
            a0 = fmaf(v[k].z, w0[k*4+2], a0); a1 = fmaf(v[k].z, w1[k*4+2], a1);
            a0 = fmaf(v[k].w, w0[k*4+3], a0); a1 = fmaf(v[k].w, w1[k*4+3], a1);
        }
#pragma unroll
        for (int off = 16; off > 0; off >>= 1) {
            a0 += __shfl_down_sync(0xffffffffu, a0, off);
            a1 += __shfl_down_sync(0xffffffffu, a1, off);
        }
        if (lane == 0) {
            g_l0[row] = a0 + b0;
            g_l1[row] = a1 + b1;
        }

        if (nrow >= NROWS) break;
        row = nrow;
#pragma unroll
        for (int k = 0; k < 4; k++) v[k] = nv[k];
    }
}

// ---------------------------------------------------------------------------
// Kernel 2: per-chunk transition function. One warp per 128-step chunk.
// Ordered reduce with ASCENDING offsets (contiguous segments only).
// ---------------------------------------------------------------------------
__global__ void __launch_bounds__(256) chunkfn_kernel()
{
    const int lane  = threadIdx.x & 31;
    const int warp  = threadIdx.x >> 5;
    const int chunk = blockIdx.x * 8 + warp;     // grid = 128 blocks

    const size_t base = (size_t)chunk * CHUNK + (size_t)lane * 4;
    float4 v0 = *reinterpret_cast<const float4*>(g_l0 + base);
    float4 v1 = *reinterpret_cast<const float4*>(g_l1 + base);

    unsigned f = step_fn(v0.x, v1.x);
    f = compose_fn(f, step_fn(v0.y, v1.y));
    f = compose_fn(f, step_fn(v0.z, v1.z));
    f = compose_fn(f, step_fn(v0.w, v1.w));

    // ordered tree reduce: lane 0 ends with f0∘f1∘...∘f31 (time order)
#pragma unroll
    for (int off = 1; off < 32; off <<= 1) {
        unsigned other = __shfl_down_sync(0xffffffffu, f, off);
        f = compose_fn(f, other);
    }
    if (lane == 0) g_chunkfn[chunk] = (unsigned char)f;
}

// ---------------------------------------------------------------------------
// Kernel 3: replay. 1024 blocks x 128 threads. Warp shfl scans.
// ---------------------------------------------------------------------------
__global__ void __launch_bounds__(128) replay_kernel(float* __restrict__ out)
{
    const int blk  = blockIdx.x;
    const int row  = blk / CPR;
    const int c    = blk % CPR;
    const int t    = threadIdx.x;
    const int lane = t & 31;
    const int w    = t >> 5;

    __shared__ unsigned sAgg[4];
    __shared__ unsigned s_inflag;

    const size_t base = (size_t)row * L + (size_t)c * CHUNK;

    const float l0 = g_l0[base + t];
    const float l1 = g_l1[base + t];

    // warp inclusive scan of step functions (time order = lane order)
    unsigned incl = step_fn(l0, l1);
#pragma unroll
    for (int off = 1; off < 32; off <<= 1) {
        unsigned p = __shfl_up_sync(0xffffffffu, incl, off);
        if (lane >= off) incl = compose_fn(p, incl);
    }
    if (lane == 31) sAgg[w] = incl;

    // warp 0: incoming flag = composition of cf[row*CPR .. row*CPR+c-1] applied to 0.
    if (w == 0) {
        const unsigned char* cf = g_chunkfn + row * CPR;
        unsigned a = (2 * lane     < c) ? (unsigned)cf[2 * lane]     : FN_ID;
        unsigned b = (2 * lane + 1 < c) ? (unsigned)cf[2 * lane + 1] : FN_ID;
        unsigned v = compose_fn(a, b);
#pragma unroll
        for (int off = 1; off < 32; off <<= 1) {
            unsigned p = __shfl_up_sync(0xffffffffu, v, off);
            if (lane >= off) v = compose_fn(p, v);
        }
        int src = ((c + 1) >> 1) - 1;                 // ceil(c/2)-1 (valid for c>0)
        unsigned F = __shfl_sync(0xffffffffu, v, src < 0 ? 0 : src);
        if (lane == 0) s_inflag = (c == 0) ? 0u : (F & 3u);
    }
    __syncthreads();

    // prefix of preceding warps (<=3 composes, contiguous order)
    unsigned wpre = FN_ID;
#pragma unroll
    for (int ww = 0; ww < 3; ww++)
        if (ww < w) wpre = compose_fn(wpre, sAgg[ww]);

    // exclusive within warp
    unsigned ex = __shfl_up_sync(0xffffffffu, incl, 1);
    if (lane == 0) ex = FN_ID;
    unsigned X = compose_fn(wpre, ex);

    const unsigned inflag = s_inflag;
    unsigned flag = (X >> (2 * inflag)) & 3u;

    float lm1 = (flag > 0u) ? (l1 + NEG) : l1;
    int pred = (lm1 > l0) ? 1 : 0;

    float mx    = fmaxf(l0, lm1);
    float other = pred ? l0 : lm1;
    float g = -log1pf(expf((other - mx) * (1.0f / TAU)));

    out[base + t]                 = (float)pred;
    out[(size_t)NROWS + base + t] = g;
}

// ---------------------------------------------------------------------------
extern "C" void kernel_launch(void* const* d_in, const int* in_sizes, int n_in,
                              void* d_out, int out_size)
{
    const float* x    = (const float*)d_in[0];   // [16, 8192, 512] f32
    // d_in[1] = label (int32) — unused
    const float* W    = (const float*)d_in[2];   // [512, 2] f32
    const float* bias = (const float*)d_in[3];   // [2] f32
    float* out = (float*)d_out;

    gemv_kernel<<<GEMV_BLOCKS, 256>>>(x, W, bias);
    chunkfn_kernel<<<NCHUNKS / 8, 256>>>();
    replay_kernel<<<NCHUNKS, 128>>>(out);
}

// round 7
// speedup vs baseline: 1.1535x; 1.0506x over previous
#include <cuda_runtime.h>
#include <math.h>
#include <stdint.h>

// Problem constants
#define BS 16
#define L  8192
#define D  512
#define NROWS (BS * L)          // 131072 timestep-rows
#define CHUNK 128               // timesteps per chunk
#define NCHUNKS (NROWS / CHUNK) // 1024
#define CPR (L / CHUNK)         // 64 chunks per batch row
#define TAU 2.0f
#define NEG -10000.0f
#define FN_ID 0xE4u             // identity fn: 0,1,2,3 -> 0,1,2,3

#define TILE_ROWS 8
#define NTILES (NROWS / TILE_ROWS)   // 16384
#define GEMV_BLOCKS 1184             // 8 * 148 SMs

// Scratch (device globals — no allocation). SoA logits for coalesced access.
__device__ float g_l0[NROWS];
__device__ float g_l1[NROWS];
__device__ unsigned char g_chunkfn[NCHUNKS];

// fn: {0..3}->{0..3} packed 2 bits/entry. compose(first, second)(s) = second(first(s))
__device__ __forceinline__ unsigned compose_fn(unsigned first, unsigned second) {
    unsigned r = 0;
#pragma unroll
    for (int s = 0; s < 4; s++) {
        unsigned fs = (first >> (2 * s)) & 3u;
        r |= ((second >> (2 * fs)) & 3u) << (2 * s);
    }
    return r;
}

__device__ __forceinline__ unsigned step_fn(float l0, float l1) {
    unsigned u = (l1 > l0) ? 1u : 0u;           // decision if flag==0
    unsigned m = ((l1 + NEG) > l0) ? 1u : 0u;   // decision if flag>0
    unsigned e0 = u ? 3u : 0u;
    unsigned e1 = m ? 3u : 0u;
    unsigned e2 = m ? 3u : 1u;
    unsigned e3 = m ? 3u : 2u;
    return e0 | (e1 << 2) | (e2 << 4) | (e3 << 6);
}

// ---------------------------------------------------------------------------
// cp.async helpers
// ---------------------------------------------------------------------------
__device__ __forceinline__ void fill_stage(float4* dst, const float4* src,
                                           int tid, bool valid)
{
    if (valid) {
#pragma unroll
        for (int i = 0; i < 4; i++) {
            uint32_t s = (uint32_t)__cvta_generic_to_shared(dst + tid + 256 * i);
            const float4* g = src + tid + 256 * i;
            asm volatile("cp.async.cg.shared.global [%0], [%1], 16;\n"
                         :: "r"(s), "l"(g) : "memory");
        }
    }
    // ALWAYS commit (possibly empty group) so group accounting stays uniform.
    asm volatile("cp.async.commit_group;\n" ::: "memory");
}

// ---------------------------------------------------------------------------
// Kernel 1: GEMV via cp.async double-buffered smem pipeline.
// Block processes 8-row (16KB, contiguous) tiles. Warp w reduces row w.
// ---------------------------------------------------------------------------
__global__ void __launch_bounds__(256) gemv_kernel(
    const float* __restrict__ x,
    const float* __restrict__ W,
    const float* __restrict__ bias)
{
    __shared__ float4 stage[2][TILE_ROWS * 128];   // 2 x 16KB
    __shared__ float sW[D * 2];

    const int tid  = threadIdx.x;
    const int lane = tid & 31;
    const int warp = tid >> 5;

    for (int i = tid; i < D * 2; i += 256) sW[i] = W[i];
    __syncthreads();

    // per-lane W slice: d = lane*4 + k*128 + j
    float w0[16], w1[16];
#pragma unroll
    for (int k = 0; k < 4; k++)
#pragma unroll
        for (int j = 0; j < 4; j++) {
            int d = lane * 4 + k * 128 + j;
            w0[k * 4 + j] = sW[d * 2 + 0];
            w1[k * 4 + j] = sW[d * 2 + 1];
        }
    const float b0 = bias[0], b1 = bias[1];

    const float4* x4 = reinterpret_cast<const float4*>(x);
    const int stride = GEMV_BLOCKS;
    const int t0 = blockIdx.x;

    // prologue: prime both stages
    fill_stage(stage[0], x4 + (size_t)t0 * (TILE_ROWS * 128), tid, t0 < NTILES);
    fill_stage(stage[1], x4 + (size_t)(t0 + stride) * (TILE_ROWS * 128), tid,
               (t0 + stride) < NTILES);

    int s = 0;
#pragma unroll 1
    for (int t = t0; t < NTILES; t += stride, s ^= 1) {
        asm volatile("cp.async.wait_group 1;\n" ::: "memory");
        __syncthreads();

        // compute: warp handles row `warp` of this tile
        const float4* rp = stage[s] + warp * 128;
        float a0 = 0.f, a1 = 0.f;
#pragma unroll
        for (int k = 0; k < 4; k++) {
            float4 v = rp[lane + 32 * k];
            a0 = fmaf(v.x, w0[k*4+0], a0); a1 = fmaf(v.x, w1[k*4+0], a1);
            a0 = fmaf(v.y, w0[k*4+1], a0); a1 = fmaf(v.y, w1[k*4+1], a1);
            a0 = fmaf(v.z, w0[k*4+2], a0); a1 = fmaf(v.z, w1[k*4+2], a1);
            a0 = fmaf(v.w, w0[k*4+3], a0); a1 = fmaf(v.w, w1[k*4+3], a1);
        }

        // combined dual reduction: 6 shfls.
        a0 += __shfl_xor_sync(0xffffffffu, a0, 16);
        a1 += __shfl_xor_sync(0xffffffffu, a1, 16);
        float v = (lane < 16) ? a0 : a1;
#pragma unroll
        for (int off = 8; off > 0; off >>= 1)
            v += __shfl_xor_sync(0xffffffffu, v, off);
        // lanes 0-15 hold full a0 sum, lanes 16-31 full a1 sum

        const int row = t * TILE_ROWS + warp;
        if (lane == 0)  g_l0[row] = v + b0;
        if (lane == 16) g_l1[row] = v + b1;

        __syncthreads();   // everyone done reading stage s before refill

        fill_stage(stage[s], x4 + (size_t)(t + 2 * stride) * (TILE_ROWS * 128),
                   tid, (t + 2 * stride) < NTILES);
    }
}

// ---------------------------------------------------------------------------
// Kernel 2: per-chunk transition function. One warp per 128-step chunk.
// Ordered reduce with ASCENDING offsets (contiguous segments only).
// ---------------------------------------------------------------------------
__global__ void __launch_bounds__(256) chunkfn_kernel()
{
    const int lane  = threadIdx.x & 31;
    const int warp  = threadIdx.x >> 5;
    const int chunk = blockIdx.x * 8 + warp;     // grid = 128 blocks

    const size_t base = (size_t)chunk * CHUNK + (size_t)lane * 4;
    float4 v0 = *reinterpret_cast<const float4*>(g_l0 + base);
    float4 v1 = *reinterpret_cast<const float4*>(g_l1 + base);

    unsigned f = step_fn(v0.x, v1.x);
    f = compose_fn(f, step_fn(v0.y, v1.y));
    f = compose_fn(f, step_fn(v0.z, v1.z));
    f = compose_fn(f, step_fn(v0.w, v1.w));

    // ordered tree reduce: lane 0 ends with f0∘f1∘...∘f31 (time order)
#pragma unroll
    for (int off = 1; off < 32; off <<= 1) {
        unsigned other = __shfl_down_sync(0xffffffffu, f, off);
        f = compose_fn(f, other);
    }
    if (lane == 0) g_chunkfn[chunk] = (unsigned char)f;
}

// ---------------------------------------------------------------------------
// Kernel 3: replay. 1024 blocks x 128 threads. Warp shfl scans.
// ---------------------------------------------------------------------------
__global__ void __launch_bounds__(128) replay_kernel(float* __restrict__ out)
{
    const int blk  = blockIdx.x;
    const int row  = blk / CPR;
    const int c    = blk % CPR;
    const int t    = threadIdx.x;
    const int lane = t & 31;
    const int w    = t >> 5;

    __shared__ unsigned sAgg[4];
    __shared__ unsigned s_inflag;

    const size_t base = (size_t)row * L + (size_t)c * CHUNK;

    const float l0 = g_l0[base + t];
    const float l1 = g_l1[base + t];

    // warp inclusive scan of step functions (time order = lane order)
    unsigned incl = step_fn(l0, l1);
#pragma unroll
    for (int off = 1; off < 32; off <<= 1) {
        unsigned p = __shfl_up_sync(0xffffffffu, incl, off);
        if (lane >= off) incl = compose_fn(p, incl);
    }
    if (lane == 31) sAgg[w] = incl;

    // warp 0: incoming flag = composition of cf[row*CPR .. row*CPR+c-1] applied to 0.
    if (w == 0) {
        const unsigned char* cf = g_chunkfn + row * CPR;
        unsigned a = (2 * lane     < c) ? (unsigned)cf[2 * lane]     : FN_ID;
        unsigned b = (2 * lane + 1 < c) ? (unsigned)cf[2 * lane + 1] : FN_ID;
        unsigned v = compose_fn(a, b);
#pragma unroll
        for (int off = 1; off < 32; off <<= 1) {
            unsigned p = __shfl_up_sync(0xffffffffu, v, off);
            if (lane >= off) v = compose_fn(p, v);
        }
        int src = ((c + 1) >> 1) - 1;                 // ceil(c/2)-1 (valid for c>0)
        unsigned F = __shfl_sync(0xffffffffu, v, src < 0 ? 0 : src);
        if (lane == 0) s_inflag = (c == 0) ? 0u : (F & 3u);
    }
    __syncthreads();

    // prefix of preceding warps (<=3 composes, contiguous order)
    unsigned wpre = FN_ID;
#pragma unroll
    for (int ww = 0; ww < 3; ww++)
        if (ww < w) wpre = compose_fn(wpre, sAgg[ww]);

    // exclusive within warp
    unsigned ex = __shfl_up_sync(0xffffffffu, incl, 1);
    if (lane == 0) ex = FN_ID;
    unsigned X = compose_fn(wpre, ex);

    const unsigned inflag = s_inflag;
    unsigned flag = (X >> (2 * inflag)) & 3u;

    float lm1 = (flag > 0u) ? (l1 + NEG) : l1;
    int pred = (lm1 > l0) ? 1 : 0;

    float mx    = fmaxf(l0, lm1);
    float other = pred ? l0 : lm1;
    float g = -log1pf(expf((other - mx) * (1.0f / TAU)));

    out[base + t]                 = (float)pred;
    out[(size_t)NROWS + base + t] = g;
}

// ---------------------------------------------------------------------------
extern "C" void kernel_launch(void* const* d_in, const int* in_sizes, int n_in,
                              void* d_out, int out_size)
{
    const float* x    = (const float*)d_in[0];   // [16, 8192, 512] f32
    // d_in[1] = label (int32) — unused
    const float* W    = (const float*)d_in[2];   // [512, 2] f32
    const float* bias = (const float*)d_in[3];   // [2] f32
    float* out = (float*)d_out;

    gemv_kernel<<<GEMV_BLOCKS, 256>>>(x, W, bias);
    chunkfn_kernel<<<NCHUNKS / 8, 256>>>();
    replay_kernel<<<NCHUNKS, 128>>>(out);
}